// round 2
// baseline (speedup 1.0000x reference)
#include <cuda_runtime.h>

#define D        64
#define EPSV     0.1f
#define MAXN     225000

// Scratch (no allocations allowed): ping-pong embedding buffers + degree info.
__device__ float        g_xA[MAXN * D];
__device__ float        g_xB[MAXN * D];
__device__ float        g_dinv[MAXN];
__device__ unsigned int g_deg[MAXN];

// ---------------------------------------------------------------------------
// init: zero d_out (accumulator), zero degrees, copy concat(Gu,Gi) into g_xA.
// ---------------------------------------------------------------------------
__global__ void init_kernel(const float* __restrict__ Gu,
                            const float* __restrict__ Gi,
                            float* __restrict__ acc,
                            int U, int N) {
    long long i = (long long)blockIdx.x * blockDim.x + threadIdx.x;
    long long total4 = (long long)N * (D / 4);          // float4 elements
    if (i < total4) {
        long long ubound4 = (long long)U * (D / 4);
        float4 v;
        if (i < ubound4) v = ((const float4*)Gu)[i];
        else             v = ((const float4*)Gi)[i - ubound4];
        ((float4*)g_xA)[i] = v;
        ((float4*)acc)[i]  = make_float4(0.f, 0.f, 0.f, 0.f);
    }
    if (i < N) g_deg[i] = 0u;
}

// ---------------------------------------------------------------------------
// degree: histogram of dst
// ---------------------------------------------------------------------------
__global__ void deg_kernel(const int* __restrict__ dst, int E) {
    int e = blockIdx.x * blockDim.x + threadIdx.x;
    if (e < E) atomicAdd(&g_deg[dst[e]], 1u);
}

__global__ void dinv_kernel(int N) {
    int n = blockIdx.x * blockDim.x + threadIdx.x;
    if (n < N) {
        unsigned int d = g_deg[n];
        g_dinv[n] = d ? rsqrtf((float)d) : 0.f;
    }
}

// ---------------------------------------------------------------------------
// zero the destination buffer for the next SpMM (layer parity picks buffer)
// ---------------------------------------------------------------------------
__global__ void zero_kernel(int layer, int N) {
    long long i = (long long)blockIdx.x * blockDim.x + threadIdx.x;
    long long total4 = (long long)N * (D / 4);
    if (i < total4) {
        float* y = (layer & 1) ? g_xA : g_xB;
        ((float4*)y)[i] = make_float4(0.f, 0.f, 0.f, 0.f);
    }
}

// ---------------------------------------------------------------------------
// SpMM scatter: warp per edge. y[dst] += dinv[src]*dinv[dst] * x[src]
// Lane L handles floats [2L, 2L+1] of the 64-wide row (contiguous 256B/warp).
// ---------------------------------------------------------------------------
__global__ void scatter_kernel(const int* __restrict__ src,
                               const int* __restrict__ dst,
                               int E, int layer) {
    long long t = (long long)blockIdx.x * blockDim.x + threadIdx.x;
    int e = (int)(t >> 5);
    if (e >= E) return;
    int lane = threadIdx.x & 31;

    const float* x = (layer & 1) ? g_xB : g_xA;
    float*       y = (layer & 1) ? g_xA : g_xB;

    int s = __ldg(src + e);
    int d = __ldg(dst + e);
    float nrm = __ldg(g_dinv + s) * __ldg(g_dinv + d);

    float2 v = __ldg((const float2*)(x + (long long)s * D) + lane);
    float* yp = y + (long long)d * D + lane * 2;
    atomicAdd(yp,     v.x * nrm);
    atomicAdd(yp + 1, v.y * nrm);
}

// ---------------------------------------------------------------------------
// perturb + accumulate: warp per node.
//   x += sign(x) * (noise_row / max(||noise_row||,1e-12)) * EPS  (in place)
//   acc += x / 3
// ---------------------------------------------------------------------------
__device__ __forceinline__ float sgnf(float v) {
    return (v > 0.f) ? 1.f : ((v < 0.f) ? -1.f : 0.f);
}

__global__ void perturb_kernel(const float* __restrict__ noise,
                               float* __restrict__ acc,
                               int N, int layer) {
    long long t = (long long)blockIdx.x * blockDim.x + threadIdx.x;
    int n = (int)(t >> 5);
    if (n >= N) return;
    int lane = threadIdx.x & 31;

    float* x = (layer & 1) ? g_xA : g_xB;   // buffer written by this layer's scatter

    const float2* nzp = (const float2*)(noise + (long long)n * D);
    float2 nv = __ldg(nzp + lane);
    float ss = nv.x * nv.x + nv.y * nv.y;
    #pragma unroll
    for (int o = 16; o; o >>= 1) ss += __shfl_xor_sync(0xFFFFFFFFu, ss, o);
    float scale = EPSV / fmaxf(sqrtf(ss), 1e-12f);

    float2* xp = (float2*)(x + (long long)n * D) + lane;
    float2 xv = *xp;
    xv.x += sgnf(xv.x) * nv.x * scale;
    xv.y += sgnf(xv.y) * nv.y * scale;
    *xp = xv;

    float2* ap = (float2*)(acc + (long long)n * D) + lane;
    float2 av = *ap;
    const float third = 1.f / 3.f;
    av.x += xv.x * third;
    av.y += xv.y * third;
    *ap = av;
}

// ---------------------------------------------------------------------------
extern "C" void kernel_launch(void* const* d_in, const int* in_sizes, int n_in,
                              void* d_out, int out_size) {
    const float* Gu = (const float*)d_in[0];
    const float* Gi = (const float*)d_in[1];
    const float* nz = (const float*)d_in[2];
    const int*   ei = (const int*)d_in[3];

    int U = in_sizes[0] / D;
    int I = in_sizes[1] / D;
    int N = U + I;
    int E = in_sizes[3] / 2;

    const int* src = ei;
    const int* dst = ei + E;
    float* acc = (float*)d_out;

    const int TPB = 256;
    long long total4 = (long long)N * (D / 4);
    int blks_elem = (int)((total4 + TPB - 1) / TPB);
    int blks_E    = (E + TPB - 1) / TPB;
    int blks_N    = (N + TPB - 1) / TPB;
    long long edge_threads = (long long)E * 32;
    int blks_edge = (int)((edge_threads + TPB - 1) / TPB);
    long long node_threads = (long long)N * 32;
    int blks_node = (int)((node_threads + TPB - 1) / TPB);

    init_kernel<<<blks_elem, TPB>>>(Gu, Gi, acc, U, N);
    deg_kernel<<<blks_E, TPB>>>(dst, E);
    dinv_kernel<<<blks_N, TPB>>>(N);

    for (int layer = 0; layer < 3; layer++) {
        zero_kernel<<<blks_elem, TPB>>>(layer, N);
        scatter_kernel<<<blks_edge, TPB>>>(src, dst, E, layer);
        perturb_kernel<<<blks_node, TPB>>>(nz + (long long)layer * N * D,
                                           acc, N, layer);
    }
}

// round 3
// speedup vs baseline: 2.8875x; 2.8875x over previous
#include <cuda_runtime.h>

#define D     64
#define EPSV  0.1f
#define MAXN  225000
#define MAXE  3200000
#define NBLK  512            // >= ceil(MAXN/1024)

// Scratch (no allocations allowed).
__device__ float        g_xA[MAXN * D];
__device__ float        g_xB[MAXN * D];
__device__ float        g_dinv[MAXN];
__device__ unsigned int g_deg[MAXN];
__device__ unsigned int g_bsum[NBLK];
__device__ unsigned int g_boff[NBLK];
__device__ int          g_rowptr[MAXN + 1];
__device__ int          g_cursor[MAXN];
__device__ int2         g_cw[MAXE];     // {src_col, weight_bits}

// ---------------------------------------------------------------------------
__global__ void init_kernel(const float* __restrict__ Gu,
                            const float* __restrict__ Gi,
                            int U, int N) {
    long long i = (long long)blockIdx.x * blockDim.x + threadIdx.x;
    long long total4 = (long long)N * (D / 4);
    if (i < total4) {
        long long ubound4 = (long long)U * (D / 4);
        float4 v;
        if (i < ubound4) v = ((const float4*)Gu)[i];
        else             v = ((const float4*)Gi)[i - ubound4];
        ((float4*)g_xA)[i] = v;
    }
    if (i < N) g_deg[i] = 0u;
}

__global__ void deg_kernel(const int* __restrict__ dst, int E) {
    int e = blockIdx.x * blockDim.x + threadIdx.x;
    if (e < E) atomicAdd(&g_deg[dst[e]], 1u);
}

__global__ void dinv_kernel(int N) {
    int n = blockIdx.x * blockDim.x + threadIdx.x;
    if (n < N) {
        unsigned int d = g_deg[n];
        g_dinv[n] = d ? rsqrtf((float)d) : 0.f;
    }
}

// ---------------------------------------------------------------------------
// Exclusive scan of g_deg -> g_rowptr (3 kernels, tiles of 1024).
// ---------------------------------------------------------------------------
__global__ void tile_reduce(int N) {
    int i = blockIdx.x * 1024 + threadIdx.x;
    int lane = threadIdx.x & 31, wid = threadIdx.x >> 5;
    unsigned v = (i < N) ? g_deg[i] : 0u;
    #pragma unroll
    for (int o = 16; o; o >>= 1) v += __shfl_down_sync(0xFFFFFFFFu, v, o);
    __shared__ unsigned ws[32];
    if (lane == 0) ws[wid] = v;
    __syncthreads();
    if (wid == 0) {
        v = ws[lane];
        #pragma unroll
        for (int o = 16; o; o >>= 1) v += __shfl_down_sync(0xFFFFFFFFu, v, o);
        if (lane == 0) g_bsum[blockIdx.x] = v;
    }
}

__global__ void scan_bsums(int B) {           // single block, 1024 threads
    __shared__ unsigned sh[1024];
    int tid = threadIdx.x;
    unsigned v = (tid < B) ? g_bsum[tid] : 0u;
    sh[tid] = v;
    __syncthreads();
    for (int off = 1; off < 1024; off <<= 1) {
        unsigned t = (tid >= off) ? sh[tid - off] : 0u;
        __syncthreads();
        sh[tid] += t;
        __syncthreads();
    }
    if (tid < B) g_boff[tid] = sh[tid] - v;   // exclusive
}

__global__ void emit_rowptr(int N, int E) {
    int b = blockIdx.x, tid = threadIdx.x;
    int lane = tid & 31, wid = tid >> 5;
    int i = b * 1024 + tid;
    unsigned v = (i < N) ? g_deg[i] : 0u;
    unsigned x = v;
    #pragma unroll
    for (int o = 1; o < 32; o <<= 1) {
        unsigned t = __shfl_up_sync(0xFFFFFFFFu, x, o);
        if (lane >= o) x += t;
    }
    __shared__ unsigned wsum[32];
    if (lane == 31) wsum[wid] = x;
    __syncthreads();
    if (wid == 0) {
        unsigned w = wsum[lane], orig = w;
        #pragma unroll
        for (int o = 1; o < 32; o <<= 1) {
            unsigned t = __shfl_up_sync(0xFFFFFFFFu, w, o);
            if (lane >= o) w += t;
        }
        wsum[lane] = w - orig;
    }
    __syncthreads();
    unsigned ex = (x - v) + wsum[wid] + g_boff[b];
    if (i < N) {
        g_rowptr[i] = (int)ex;
        g_cursor[i] = (int)ex;
        if (i == N - 1) g_rowptr[N] = (int)(ex + v);
    }
}

// ---------------------------------------------------------------------------
__global__ void fill_kernel(const int* __restrict__ src,
                            const int* __restrict__ dst, int E) {
    int e = blockIdx.x * blockDim.x + threadIdx.x;
    if (e >= E) return;
    int s = __ldg(src + e);
    int d = __ldg(dst + e);
    int pos = atomicAdd(&g_cursor[d], 1);
    float w = __ldg(g_dinv + s) * __ldg(g_dinv + d);
    g_cw[pos] = make_int2(s, __float_as_int(w));
}

// ---------------------------------------------------------------------------
// Fused gather SpMM + noise perturbation + output accumulation.
// Warp per node; lane holds float2 of the 64-wide row.
// ---------------------------------------------------------------------------
__device__ __forceinline__ float sgnf(float v) {
    return (v > 0.f) ? 1.f : ((v < 0.f) ? -1.f : 0.f);
}

__global__ void gather_perturb(const float* __restrict__ noise,
                               float* __restrict__ acc,
                               int N, int layer) {
    long long t = (long long)blockIdx.x * blockDim.x + threadIdx.x;
    int n = (int)(t >> 5);
    if (n >= N) return;
    int lane = threadIdx.x & 31;

    const float* x  = (layer & 1) ? g_xB : g_xA;
    float*       xn = (layer & 1) ? g_xA : g_xB;

    int beg = __ldg(g_rowptr + n);
    int end = __ldg(g_rowptr + n + 1);

    float2 s = make_float2(0.f, 0.f);
    for (int j0 = beg; j0 < end; j0 += 32) {
        int jj = j0 + lane;
        int2 cw = (jj < end) ? __ldg(g_cw + jj) : make_int2(0, 0);
        int cnt = min(32, end - j0);
        for (int k = 0; k < cnt; k++) {
            int   cc = __shfl_sync(0xFFFFFFFFu, cw.x, k);
            float ww = __int_as_float(__shfl_sync(0xFFFFFFFFu, cw.y, k));
            float2 v = __ldg((const float2*)(x + (long long)cc * D) + lane);
            s.x += v.x * ww;
            s.y += v.y * ww;
        }
    }

    // perturb: s += sign(s) * (noise_row / max(||noise_row||,1e-12)) * EPS
    float2 nv = __ldg((const float2*)(noise + (long long)n * D) + lane);
    float ss = nv.x * nv.x + nv.y * nv.y;
    #pragma unroll
    for (int o = 16; o; o >>= 1) ss += __shfl_xor_sync(0xFFFFFFFFu, ss, o);
    float scale = EPSV / fmaxf(sqrtf(ss), 1e-12f);
    s.x += sgnf(s.x) * nv.x * scale;
    s.y += sgnf(s.y) * nv.y * scale;

    ((float2*)(xn + (long long)n * D))[lane] = s;

    const float third = 1.f / 3.f;
    float2* ap = (float2*)(acc + (long long)n * D) + lane;
    if (layer == 0) {
        *ap = make_float2(s.x * third, s.y * third);
    } else {
        float2 av = *ap;
        av.x += s.x * third;
        av.y += s.y * third;
        *ap = av;
    }
}

// ---------------------------------------------------------------------------
extern "C" void kernel_launch(void* const* d_in, const int* in_sizes, int n_in,
                              void* d_out, int out_size) {
    const float* Gu = (const float*)d_in[0];
    const float* Gi = (const float*)d_in[1];
    const float* nz = (const float*)d_in[2];
    const int*   ei = (const int*)d_in[3];

    int U = in_sizes[0] / D;
    int I = in_sizes[1] / D;
    int N = U + I;
    int E = in_sizes[3] / 2;

    const int* src = ei;
    const int* dst = ei + E;
    float* acc = (float*)d_out;

    const int TPB = 256;
    long long total4 = (long long)N * (D / 4);
    int blks_elem = (int)((total4 + TPB - 1) / TPB);
    int blks_E    = (E + TPB - 1) / TPB;
    int blks_N    = (N + TPB - 1) / TPB;
    int B         = (N + 1023) / 1024;
    long long node_threads = (long long)N * 32;
    int blks_node = (int)((node_threads + TPB - 1) / TPB);

    init_kernel<<<blks_elem, TPB>>>(Gu, Gi, U, N);
    deg_kernel<<<blks_E, TPB>>>(dst, E);
    dinv_kernel<<<blks_N, TPB>>>(N);
    tile_reduce<<<B, 1024>>>(N);
    scan_bsums<<<1, 1024>>>(B);
    emit_rowptr<<<B, 1024>>>(N, E);
    fill_kernel<<<blks_E, TPB>>>(src, dst, E);

    for (int layer = 0; layer < 3; layer++) {
        gather_perturb<<<blks_node, TPB>>>(nz + (long long)layer * N * D,
                                           acc, N, layer);
    }
}